// round 12
// baseline (speedup 1.0000x reference)
#include <cuda_runtime.h>
#include <math.h>
#include <stdint.h>

// Problem constants
#define NB     8
#define TT     64
#define JJ     25
#define CC     256       // D_MODEL
#define DI     512       // D_INNER
#define DS     16        // D_STATE
#define DTR    16        // DT_RANK
#define BTOT   (NB*JJ)   // 200
#define NROWS  (BTOT*TT) // 12800

// ---------------- scratch ----------------
__device__ float g_xc [NROWS * DI];
__device__ float g_xc2[NROWS * DI];
__device__ float g_z  [NROWS * DI];
__device__ float g_dt [NROWS * DI];
__device__ float g_y  [NROWS * DI];
__device__ float g_Bm [NROWS * DS];
__device__ float g_Cm [NROWS * DS];

// ---------------- helpers ----------------
__device__ __forceinline__ float silu_f(float v) { return v / (1.0f + __expf(-v)); }
__device__ __forceinline__ float softplus_f(float v) {
    return fmaxf(v, 0.0f) + log1pf(__expf(-fabsf(v)));
}
__device__ __forceinline__ uint32_t f2t(float f) {
    uint32_t u; asm("cvt.rna.tf32.f32 %0, %1;" : "=r"(u) : "f"(f)); return u;
}
__device__ __forceinline__ void mma8(float* c, uint32_t a0, uint32_t a1, uint32_t a2,
                                     uint32_t a3, uint32_t b0, uint32_t b1) {
    asm volatile(
        "mma.sync.aligned.m16n8k8.row.col.f32.tf32.tf32.f32 "
        "{%0,%1,%2,%3},{%4,%5,%6,%7},{%8,%9},{%0,%1,%2,%3};"
        : "+f"(c[0]), "+f"(c[1]), "+f"(c[2]), "+f"(c[3])
        : "r"(a0), "r"(a1), "r"(a2), "r"(a3), "r"(b0), "r"(b1));
}

// ---------------- k1: in-projection GEMM (tf32 mma) — 379.7us-build verbatim --------
__global__ __launch_bounds__(256) void k1_gemm_in(const float* __restrict__ x,
                                                  const float* __restrict__ W) {
    __shared__ uint32_t sA[64][36];
    __shared__ uint32_t sB[128][36];
    const int tid = threadIdx.x, lane = tid & 31, warp = tid >> 5;
    const int lr = lane >> 2, lk = lane & 3;
    const int b = blockIdx.x, n0 = blockIdx.y * 128;
    const int n = b / 25, j = b - n * 25;
    const float* xbase = x + ((size_t)(n * TT) * JJ + j) * CC;
    const int wr = (warp >> 2) * 32, wc = (warp & 3) * 32;

    float acc[2][4][4];
    #pragma unroll
    for (int i = 0; i < 2; i++)
        #pragma unroll
        for (int jj = 0; jj < 4; jj++)
            #pragma unroll
            for (int q = 0; q < 4; q++) acc[i][jj][q] = 0.0f;

    const int ar = tid >> 2, ac = (tid & 3) * 8;
    const int br = tid >> 1, bc = (tid & 1) * 16;

    for (int c0 = 0; c0 < CC; c0 += 32) {
        __syncthreads();
        {
            const float4* p = (const float4*)(xbase + (size_t)ar * JJ * CC + c0 + ac);
            float4 v0 = p[0], v1 = p[1];
            sA[ar][ac+0]=f2t(v0.x); sA[ar][ac+1]=f2t(v0.y); sA[ar][ac+2]=f2t(v0.z); sA[ar][ac+3]=f2t(v0.w);
            sA[ar][ac+4]=f2t(v1.x); sA[ar][ac+5]=f2t(v1.y); sA[ar][ac+6]=f2t(v1.z); sA[ar][ac+7]=f2t(v1.w);
        }
        {
            const float4* p = (const float4*)(W + (size_t)(n0 + br) * CC + c0 + bc);
            #pragma unroll
            for (int q = 0; q < 4; q++) {
                float4 v = p[q];
                sB[br][bc+4*q+0]=f2t(v.x); sB[br][bc+4*q+1]=f2t(v.y);
                sB[br][bc+4*q+2]=f2t(v.z); sB[br][bc+4*q+3]=f2t(v.w);
            }
        }
        __syncthreads();
        #pragma unroll
        for (int kk = 0; kk < 4; kk++) {
            const int k0 = kk * 8;
            uint32_t a[2][4], bb[4][2];
            #pragma unroll
            for (int i = 0; i < 2; i++) {
                a[i][0] = sA[wr+16*i+lr  ][k0+lk];
                a[i][1] = sA[wr+16*i+8+lr][k0+lk];
                a[i][2] = sA[wr+16*i+lr  ][k0+lk+4];
                a[i][3] = sA[wr+16*i+8+lr][k0+lk+4];
            }
            #pragma unroll
            for (int jj = 0; jj < 4; jj++) {
                bb[jj][0] = sB[wc+8*jj+lr][k0+lk];
                bb[jj][1] = sB[wc+8*jj+lr][k0+lk+4];
            }
            #pragma unroll
            for (int i = 0; i < 2; i++)
                #pragma unroll
                for (int jj = 0; jj < 4; jj++)
                    mma8(acc[i][jj], a[i][0], a[i][1], a[i][2], a[i][3], bb[jj][0], bb[jj][1]);
        }
    }

    float* dst; int eoff;
    if (n0 < DI) { dst = g_xc; eoff = n0; } else { dst = g_z; eoff = n0 - DI; }
    #pragma unroll
    for (int i = 0; i < 2; i++) {
        const int r0 = wr + 16*i + lr, r1 = r0 + 8;
        const size_t m0r = (size_t)(b * TT + r0) * DI;
        const size_t m1r = (size_t)(b * TT + r1) * DI;
        #pragma unroll
        for (int jj = 0; jj < 4; jj++) {
            const int col = eoff + wc + 8*jj + 2*lk;
            *(float2*)&dst[m0r + col] = make_float2(acc[i][jj][0], acc[i][jj][1]);
            *(float2*)&dst[m1r + col] = make_float2(acc[i][jj][2], acc[i][jj][3]);
        }
    }
}

// ---------------- k2: depthwise causal conv + bias + SiLU — verbatim ----
__global__ void k2_conv(const float* __restrict__ conv_w,
                        const float* __restrict__ conv_b) {
    int idx = blockIdx.x * blockDim.x + threadIdx.x;
    if (idx >= NROWS * DI) return;
    int d = idx & (DI - 1);
    int m = idx >> 9;
    int t = m & 63;
    float s = conv_b[d];
    #pragma unroll
    for (int k = 0; k < 4; k++) {
        int tt = t - 3 + k;
        if (tt >= 0) s = fmaf(conv_w[d * 4 + k], g_xc[(size_t)(m - 3 + k) * DI + d], s);
    }
    g_xc2[idx] = silu_f(s);
}

// ---------------- k3: x_dbl projection + dt projection (float4 smem) — verbatim ----
__global__ __launch_bounds__(256) void k3_xproj(const float* __restrict__ Wx,
                                                const float* __restrict__ Wdt,
                                                const float* __restrict__ bdt) {
    __shared__ __align__(16) float buf[13568];
    float* sX = buf;                      // [64][68]
    float* sW = buf + 64 * 68;            // [48][68]
    const int tid = threadIdx.x;
    const int m0 = blockIdx.x * 64;
    const int row = tid >> 2, c0 = (tid & 3) * 12;

    float acc[12];
    #pragma unroll
    for (int i = 0; i < 12; i++) acc[i] = 0.0f;

    for (int k0 = 0; k0 < DI; k0 += 64) {
        __syncthreads();
        for (int idx = tid; idx < 64 * 16; idx += 256) {
            int r = idx >> 4, q = idx & 15;
            *(float4*)&sX[r * 68 + q * 4] =
                *(const float4*)&g_xc2[(size_t)(m0 + r) * DI + k0 + q * 4];
        }
        for (int idx = tid; idx < 48 * 16; idx += 256) {
            int r = idx >> 4, q = idx & 15;
            *(float4*)&sW[r * 68 + q * 4] =
                *(const float4*)&Wx[(size_t)r * DI + k0 + q * 4];
        }
        __syncthreads();
        #pragma unroll 4
        for (int q = 0; q < 16; q++) {
            float4 xv = *(const float4*)&sX[row * 68 + q * 4];
            #pragma unroll
            for (int i = 0; i < 12; i++) {
                float4 wv = *(const float4*)&sW[(c0 + i) * 68 + q * 4];
                acc[i] = fmaf(xv.x, wv.x, acc[i]);
                acc[i] = fmaf(xv.y, wv.y, acc[i]);
                acc[i] = fmaf(xv.z, wv.z, acc[i]);
                acc[i] = fmaf(xv.w, wv.w, acc[i]);
            }
        }
    }
    __syncthreads();

    float* sD   = buf;                    // [64][52]
    float* sWdt = buf + 64 * 52;          // [512][20]
    #pragma unroll
    for (int i = 0; i < 12; i++) sD[row * 52 + c0 + i] = acc[i];
    for (int idx = tid; idx < 512 * 4; idx += 256) {
        int d = idx >> 2, q = idx & 3;
        *(float4*)&sWdt[d * 20 + q * 4] = *(const float4*)&Wdt[d * 16 + q * 4];
    }
    __syncthreads();

    for (int idx = tid; idx < 64 * 32; idx += 256) {
        int r = idx >> 5, v = idx & 31;
        float val = sD[r * 52 + DTR + v];
        if (v < 16) g_Bm[(size_t)(m0 + r) * DS + v]        = val;
        else        g_Cm[(size_t)(m0 + r) * DS + (v - 16)] = val;
    }
    for (int idx = tid; idx < 64 * DI; idx += 256) {
        int r = idx >> 9, d = idx & 511;
        float a = bdt[d];
        #pragma unroll
        for (int q = 0; q < 4; q++) {
            float4 dv = *(const float4*)&sD[r * 52 + q * 4];
            float4 wv = *(const float4*)&sWdt[d * 20 + q * 4];
            a = fmaf(dv.x, wv.x, a);
            a = fmaf(dv.y, wv.y, a);
            a = fmaf(dv.z, wv.z, a);
            a = fmaf(dv.w, wv.w, a);
        }
        g_dt[(size_t)(m0 + r) * DI + d] = softplus_f(a);
    }
}

// ---------------- k4: selective scan (split-state: 2 threads/channel) --------------
// grid (200, 4), block 256. Pair of adjacent threads shares one channel:
// thread half=0 owns states 0-7, half=1 owns states 8-15; y combined via shfl.
// Doubles warp count vs 1-thread/channel (grid-capped occupancy 34% -> 67%).
__global__ __launch_bounds__(256) void k4_scan(const float* __restrict__ A_log,
                                               const float* __restrict__ D_skip) {
    const int tid  = threadIdx.x;
    const int b    = blockIdx.x;
    const int ch   = tid >> 1;            // 0..127
    const int half = tid & 1;
    const int sh   = half * 8;
    const int d    = blockIdx.y * 128 + ch;

    float Aa[8], h[8];
    bool fast = true;
    #pragma unroll
    for (int s = 0; s < 8; s++) {
        Aa[s] = -__expf(A_log[d * DS + sh + s]);
        fast = fast && (fabsf(Aa[s] + (float)(sh + s + 1)) < 1e-4f * (float)(sh + s + 1));
        h[s] = 0.0f;
    }
    const float Dk = D_skip[d];

    const size_t rowbase = (size_t)b * TT * DI + d;
    const float* pdt = g_dt  + rowbase;
    const float* pxc = g_xc2 + rowbase;
    const float* pz  = g_z   + rowbase;
    float*       py  = g_y   + rowbase;
    const float4* pB = (const float4*)(g_Bm + (size_t)b * TT * DS) + half * 2;
    const float4* pC = (const float4*)(g_Cm + (size_t)b * TT * DS) + half * 2;

    if (fast) {
        for (int t = 0; t < TT; t++) {
            const size_t o = (size_t)t * DI;
            float dt = pdt[o], xc = pxc[o], z = pz[o];
            float4 b0 = pB[t*4], b1 = pB[t*4 + 1];
            float4 c0 = pC[t*4], c1 = pC[t*4 + 1];
            float Bv[8] = {b0.x, b0.y, b0.z, b0.w, b1.x, b1.y, b1.z, b1.w};
            float Cv[8] = {c0.x, c0.y, c0.z, c0.w, c1.x, c1.y, c1.z, c1.w};

            const float du = dt * xc;
            const float w  = __expf(-dt);
            const float w2 = w*w, w4 = w2*w2, w8 = w4*w4;
            float q[8];
            q[0]=w;    q[1]=w2;    q[2]=w2*w;  q[3]=w4;
            q[4]=w4*w; q[5]=w4*w2; q[6]=w4*q[2]; q[7]=w8;
            const float f = half ? w8 : 1.0f;   // shift: p[s] = w^(sh+s+1)

            float y0 = 0.f, y1 = 0.f;
            #pragma unroll
            for (int s = 0; s < 8; s += 2) {
                h[s  ] = fmaf(q[s  ] * f, h[s  ], du * Bv[s  ]);
                h[s+1] = fmaf(q[s+1] * f, h[s+1], du * Bv[s+1]);
                y0 = fmaf(h[s  ], Cv[s  ], y0);
                y1 = fmaf(h[s+1], Cv[s+1], y1);
            }
            float y = y0 + y1;
            y += __shfl_xor_sync(0xffffffffu, y, 1);
            if (half == 0) {
                y = fmaf(xc, Dk, y);
                py[o] = y * silu_f(z);
            }
        }
    } else {
        for (int t = 0; t < TT; t++) {
            const size_t o = (size_t)t * DI;
            float dt = pdt[o], xc = pxc[o], z = pz[o];
            float4 b0 = pB[t*4], b1 = pB[t*4 + 1];
            float4 c0 = pC[t*4], c1 = pC[t*4 + 1];
            float Bv[8] = {b0.x, b0.y, b0.z, b0.w, b1.x, b1.y, b1.z, b1.w};
            float Cv[8] = {c0.x, c0.y, c0.z, c0.w, c1.x, c1.y, c1.z, c1.w};

            const float du = dt * xc;
            float y = 0.0f;
            #pragma unroll
            for (int s = 0; s < 8; s++) {
                float dA = __expf(dt * Aa[s]);
                h[s] = fmaf(dA, h[s], du * Bv[s]);
                y    = fmaf(h[s], Cv[s], y);
            }
            y += __shfl_xor_sync(0xffffffffu, y, 1);
            if (half == 0) {
                y = fmaf(xc, Dk, y);
                py[o] = y * silu_f(z);
            }
        }
    }
}

// ---------------- k5: out-proj GEMM + RMSNorm + residual — verbatim ----
__global__ __launch_bounds__(256) void k5_gemm_out(const float* __restrict__ x,
                                                   const float* __restrict__ W,
                                                   const float* __restrict__ ln_w,
                                                   float* __restrict__ out) {
    __shared__ uint32_t sA[32][36];
    __shared__ uint32_t sB[256][36];
    __shared__ float rowsq[32];
    const int tid = threadIdx.x, lane = tid & 31, warp = tid >> 5;
    const int lr = lane >> 2, lk = lane & 3;
    const int m0 = blockIdx.x * 32;
    const int wr = (warp >> 2) * 16, wc = (warp & 3) * 64;

    if (tid < 32) rowsq[tid] = 0.0f;

    float acc[8][4];
    #pragma unroll
    for (int jj = 0; jj < 8; jj++)
        #pragma unroll
        for (int q = 0; q < 4; q++) acc[jj][q] = 0.0f;

    const int ar = tid >> 3, ac = (tid & 7) * 4;
    const int br = tid;

    for (int d0 = 0; d0 < DI; d0 += 32) {
        __syncthreads();
        {
            float4 v = *(const float4*)&g_y[(size_t)(m0 + ar) * DI + d0 + ac];
            sA[ar][ac]=f2t(v.x); sA[ar][ac+1]=f2t(v.y); sA[ar][ac+2]=f2t(v.z); sA[ar][ac+3]=f2t(v.w);
        }
        {
            const float4* p = (const float4*)(W + (size_t)br * DI + d0);
            #pragma unroll
            for (int q = 0; q < 8; q++) {
                float4 v = p[q];
                sB[br][4*q]=f2t(v.x); sB[br][4*q+1]=f2t(v.y); sB[br][4*q+2]=f2t(v.z); sB[br][4*q+3]=f2t(v.w);
            }
        }
        __syncthreads();
        #pragma unroll
        for (int kk = 0; kk < 4; kk++) {
            const int k0 = kk * 8;
            uint32_t a0 = sA[wr+lr][k0+lk],   a1 = sA[wr+8+lr][k0+lk];
            uint32_t a2 = sA[wr+lr][k0+lk+4], a3 = sA[wr+8+lr][k0+lk+4];
            #pragma unroll
            for (int jj = 0; jj < 8; jj++) {
                uint32_t b0 = sB[wc+8*jj+lr][k0+lk];
                uint32_t b1 = sB[wc+8*jj+lr][k0+lk+4];
                mma8(acc[jj], a0, a1, a2, a3, b0, b1);
            }
        }
    }

    float s0 = 0.0f, s1 = 0.0f;
    #pragma unroll
    for (int jj = 0; jj < 8; jj++) {
        s0 += acc[jj][0]*acc[jj][0] + acc[jj][1]*acc[jj][1];
        s1 += acc[jj][2]*acc[jj][2] + acc[jj][3]*acc[jj][3];
    }
    s0 += __shfl_xor_sync(0xffffffffu, s0, 1); s0 += __shfl_xor_sync(0xffffffffu, s0, 2);
    s1 += __shfl_xor_sync(0xffffffffu, s1, 1); s1 += __shfl_xor_sync(0xffffffffu, s1, 2);
    if (lk == 0) { atomicAdd(&rowsq[wr + lr], s0); atomicAdd(&rowsq[wr + 8 + lr], s1); }
    __syncthreads();

    const int r0 = wr + lr, r1 = wr + 8 + lr;
    float rms0 = rsqrtf(rowsq[r0] * (1.0f / CC) + 1e-6f);
    float rms1 = rsqrtf(rowsq[r1] * (1.0f / CC) + 1e-6f);

    const int m0r = m0 + r0, m1r = m0 + r1;
    const int t0 = m0r & 63, b0_ = m0r >> 6, n_0 = b0_ / 25, j0 = b0_ - n_0 * 25;
    const int t1 = m1r & 63, b1_ = m1r >> 6, n_1 = b1_ / 25, j1 = b1_ - n_1 * 25;
    const size_t g0 = ((size_t)(n_0 * TT + t0) * JJ + j0) * CC;
    const size_t g1 = ((size_t)(n_1 * TT + t1) * JJ + j1) * CC;
    #pragma unroll
    for (int jj = 0; jj < 8; jj++) {
        const int col = wc + 8*jj + 2*lk;
        float2 lw = *(const float2*)&ln_w[col];
        float2 x0 = *(const float2*)&x[g0 + col];
        float2 x1 = *(const float2*)&x[g1 + col];
        *(float2*)&out[g0 + col] = make_float2(fmaf(acc[jj][0]*rms0, lw.x, x0.x),
                                               fmaf(acc[jj][1]*rms0, lw.y, x0.y));
        *(float2*)&out[g1 + col] = make_float2(fmaf(acc[jj][2]*rms1, lw.x, x1.x),
                                               fmaf(acc[jj][3]*rms1, lw.y, x1.y));
    }
}

// ---------------- launch ----------------
extern "C" void kernel_launch(void* const* d_in, const int* in_sizes, int n_in,
                              void* d_out, int out_size) {
    const float* x      = (const float*)d_in[0];
    const float* W_in   = (const float*)d_in[1];
    const float* conv_w = (const float*)d_in[2];
    const float* conv_b = (const float*)d_in[3];
    const float* W_xprj = (const float*)d_in[4];
    const float* W_dt   = (const float*)d_in[5];
    const float* b_dt   = (const float*)d_in[6];
    const float* A_log  = (const float*)d_in[7];
    const float* D_skip = (const float*)d_in[8];
    const float* W_out  = (const float*)d_in[9];
    const float* ln_w   = (const float*)d_in[10];
    float* out = (float*)d_out;

    k1_gemm_in<<<dim3(BTOT, 8), 256>>>(x, W_in);
    k2_conv<<<(NROWS * DI) / 256, 256>>>(conv_w, conv_b);
    k3_xproj<<<BTOT, 256>>>(W_xprj, W_dt, b_dt);
    k4_scan<<<dim3(BTOT, 4), 256>>>(A_log, D_skip);
    k5_gemm_out<<<NROWS / 32, 256>>>(x, W_out, ln_w, out);
}

// round 15
// speedup vs baseline: 1.2057x; 1.2057x over previous
#include <cuda_runtime.h>
#include <math.h>
#include <stdint.h>

// Problem constants
#define NB     8
#define TT     64
#define JJ     25
#define CC     256       // D_MODEL
#define DI     512       // D_INNER
#define DS     16        // D_STATE
#define DTR    16        // DT_RANK
#define BTOT   (NB*JJ)   // 200
#define NROWS  (BTOT*TT) // 12800

// ---------------- scratch ----------------
__device__ float g_xc [NROWS * DI];
__device__ float g_xc2[NROWS * DI];
__device__ float g_z  [NROWS * DI];
__device__ float g_dt [NROWS * DI];
__device__ float g_y  [NROWS * DI];
__device__ float g_Bm [NROWS * DS];
__device__ float g_Cm [NROWS * DS];

// ---------------- helpers ----------------
__device__ __forceinline__ float silu_f(float v) { return v / (1.0f + __expf(-v)); }
__device__ __forceinline__ float softplus_f(float v) {
    return fmaxf(v, 0.0f) + log1pf(__expf(-fabsf(v)));
}
__device__ __forceinline__ uint32_t f2t(float f) {
    uint32_t u; asm("cvt.rna.tf32.f32 %0, %1;" : "=r"(u) : "f"(f)); return u;
}
__device__ __forceinline__ void mma8(float* c, uint32_t a0, uint32_t a1, uint32_t a2,
                                     uint32_t a3, uint32_t b0, uint32_t b1) {
    asm volatile(
        "mma.sync.aligned.m16n8k8.row.col.f32.tf32.tf32.f32 "
        "{%0,%1,%2,%3},{%4,%5,%6,%7},{%8,%9},{%0,%1,%2,%3};"
        : "+f"(c[0]), "+f"(c[1]), "+f"(c[2]), "+f"(c[3])
        : "r"(a0), "r"(a1), "r"(a2), "r"(a3), "r"(b0), "r"(b1));
}

// ---------------- k1: in-projection GEMM (tf32 mma) — R10 verbatim --------
__global__ __launch_bounds__(256) void k1_gemm_in(const float* __restrict__ x,
                                                  const float* __restrict__ W) {
    __shared__ uint32_t sA[64][36];
    __shared__ uint32_t sB[128][36];
    const int tid = threadIdx.x, lane = tid & 31, warp = tid >> 5;
    const int lr = lane >> 2, lk = lane & 3;
    const int b = blockIdx.x, n0 = blockIdx.y * 128;
    const int n = b / 25, j = b - n * 25;
    const float* xbase = x + ((size_t)(n * TT) * JJ + j) * CC;
    const int wr = (warp >> 2) * 32, wc = (warp & 3) * 32;

    float acc[2][4][4];
    #pragma unroll
    for (int i = 0; i < 2; i++)
        #pragma unroll
        for (int jj = 0; jj < 4; jj++)
            #pragma unroll
            for (int q = 0; q < 4; q++) acc[i][jj][q] = 0.0f;

    const int ar = tid >> 2, ac = (tid & 3) * 8;
    const int br = tid >> 1, bc = (tid & 1) * 16;

    for (int c0 = 0; c0 < CC; c0 += 32) {
        __syncthreads();
        {
            const float4* p = (const float4*)(xbase + (size_t)ar * JJ * CC + c0 + ac);
            float4 v0 = p[0], v1 = p[1];
            sA[ar][ac+0]=f2t(v0.x); sA[ar][ac+1]=f2t(v0.y); sA[ar][ac+2]=f2t(v0.z); sA[ar][ac+3]=f2t(v0.w);
            sA[ar][ac+4]=f2t(v1.x); sA[ar][ac+5]=f2t(v1.y); sA[ar][ac+6]=f2t(v1.z); sA[ar][ac+7]=f2t(v1.w);
        }
        {
            const float4* p = (const float4*)(W + (size_t)(n0 + br) * CC + c0 + bc);
            #pragma unroll
            for (int q = 0; q < 4; q++) {
                float4 v = p[q];
                sB[br][bc+4*q+0]=f2t(v.x); sB[br][bc+4*q+1]=f2t(v.y);
                sB[br][bc+4*q+2]=f2t(v.z); sB[br][bc+4*q+3]=f2t(v.w);
            }
        }
        __syncthreads();
        #pragma unroll
        for (int kk = 0; kk < 4; kk++) {
            const int k0 = kk * 8;
            uint32_t a[2][4], bb[4][2];
            #pragma unroll
            for (int i = 0; i < 2; i++) {
                a[i][0] = sA[wr+16*i+lr  ][k0+lk];
                a[i][1] = sA[wr+16*i+8+lr][k0+lk];
                a[i][2] = sA[wr+16*i+lr  ][k0+lk+4];
                a[i][3] = sA[wr+16*i+8+lr][k0+lk+4];
            }
            #pragma unroll
            for (int jj = 0; jj < 4; jj++) {
                bb[jj][0] = sB[wc+8*jj+lr][k0+lk];
                bb[jj][1] = sB[wc+8*jj+lr][k0+lk+4];
            }
            #pragma unroll
            for (int i = 0; i < 2; i++)
                #pragma unroll
                for (int jj = 0; jj < 4; jj++)
                    mma8(acc[i][jj], a[i][0], a[i][1], a[i][2], a[i][3], bb[jj][0], bb[jj][1]);
        }
    }

    float* dst; int eoff;
    if (n0 < DI) { dst = g_xc; eoff = n0; } else { dst = g_z; eoff = n0 - DI; }
    #pragma unroll
    for (int i = 0; i < 2; i++) {
        const int r0 = wr + 16*i + lr, r1 = r0 + 8;
        const size_t m0r = (size_t)(b * TT + r0) * DI;
        const size_t m1r = (size_t)(b * TT + r1) * DI;
        #pragma unroll
        for (int jj = 0; jj < 4; jj++) {
            const int col = eoff + wc + 8*jj + 2*lk;
            *(float2*)&dst[m0r + col] = make_float2(acc[i][jj][0], acc[i][jj][1]);
            *(float2*)&dst[m1r + col] = make_float2(acc[i][jj][2], acc[i][jj][3]);
        }
    }
}

// ---------------- k2: depthwise causal conv + bias + SiLU — verbatim ----
__global__ void k2_conv(const float* __restrict__ conv_w,
                        const float* __restrict__ conv_b) {
    int idx = blockIdx.x * blockDim.x + threadIdx.x;
    if (idx >= NROWS * DI) return;
    int d = idx & (DI - 1);
    int m = idx >> 9;
    int t = m & 63;
    float s = conv_b[d];
    #pragma unroll
    for (int k = 0; k < 4; k++) {
        int tt = t - 3 + k;
        if (tt >= 0) s = fmaf(conv_w[d * 4 + k], g_xc[(size_t)(m - 3 + k) * DI + d], s);
    }
    g_xc2[idx] = silu_f(s);
}

// ---------------- k3: x_dbl projection + dt projection (float4 smem) — verbatim ----
__global__ __launch_bounds__(256) void k3_xproj(const float* __restrict__ Wx,
                                                const float* __restrict__ Wdt,
                                                const float* __restrict__ bdt) {
    __shared__ __align__(16) float buf[13568];
    float* sX = buf;                      // [64][68]
    float* sW = buf + 64 * 68;            // [48][68]
    const int tid = threadIdx.x;
    const int m0 = blockIdx.x * 64;
    const int row = tid >> 2, c0 = (tid & 3) * 12;

    float acc[12];
    #pragma unroll
    for (int i = 0; i < 12; i++) acc[i] = 0.0f;

    for (int k0 = 0; k0 < DI; k0 += 64) {
        __syncthreads();
        for (int idx = tid; idx < 64 * 16; idx += 256) {
            int r = idx >> 4, q = idx & 15;
            *(float4*)&sX[r * 68 + q * 4] =
                *(const float4*)&g_xc2[(size_t)(m0 + r) * DI + k0 + q * 4];
        }
        for (int idx = tid; idx < 48 * 16; idx += 256) {
            int r = idx >> 4, q = idx & 15;
            *(float4*)&sW[r * 68 + q * 4] =
                *(const float4*)&Wx[(size_t)r * DI + k0 + q * 4];
        }
        __syncthreads();
        #pragma unroll 4
        for (int q = 0; q < 16; q++) {
            float4 xv = *(const float4*)&sX[row * 68 + q * 4];
            #pragma unroll
            for (int i = 0; i < 12; i++) {
                float4 wv = *(const float4*)&sW[(c0 + i) * 68 + q * 4];
                acc[i] = fmaf(xv.x, wv.x, acc[i]);
                acc[i] = fmaf(xv.y, wv.y, acc[i]);
                acc[i] = fmaf(xv.z, wv.z, acc[i]);
                acc[i] = fmaf(xv.w, wv.w, acc[i]);
            }
        }
    }
    __syncthreads();

    float* sD   = buf;                    // [64][52]
    float* sWdt = buf + 64 * 52;          // [512][20]
    #pragma unroll
    for (int i = 0; i < 12; i++) sD[row * 52 + c0 + i] = acc[i];
    for (int idx = tid; idx < 512 * 4; idx += 256) {
        int d = idx >> 2, q = idx & 3;
        *(float4*)&sWdt[d * 20 + q * 4] = *(const float4*)&Wdt[d * 16 + q * 4];
    }
    __syncthreads();

    for (int idx = tid; idx < 64 * 32; idx += 256) {
        int r = idx >> 5, v = idx & 31;
        float val = sD[r * 52 + DTR + v];
        if (v < 16) g_Bm[(size_t)(m0 + r) * DS + v]        = val;
        else        g_Cm[(size_t)(m0 + r) * DS + (v - 16)] = val;
    }
    for (int idx = tid; idx < 64 * DI; idx += 256) {
        int r = idx >> 9, d = idx & 511;
        float a = bdt[d];
        #pragma unroll
        for (int q = 0; q < 4; q++) {
            float4 dv = *(const float4*)&sD[r * 52 + q * 4];
            float4 wv = *(const float4*)&sWdt[d * 20 + q * 4];
            a = fmaf(dv.x, wv.x, a);
            a = fmaf(dv.y, wv.y, a);
            a = fmaf(dv.z, wv.z, a);
            a = fmaf(dv.w, wv.w, a);
        }
        g_dt[(size_t)(m0 + r) * DI + d] = softplus_f(a);
    }
}

// ---------------- k4: selective scan — R10 version verbatim (56.8us measured) -------
// grid (200, 4), block 128: one channel per thread.
// Fast path: A = -(1..16) => dA_s = w^(s+1), w = exp(-dt): 1 MUFU per (d,t).
__global__ __launch_bounds__(128) void k4_scan(const float* __restrict__ A_log,
                                               const float* __restrict__ D_skip) {
    const int tid = threadIdx.x;
    const int b   = blockIdx.x;
    const int d   = blockIdx.y * 128 + tid;

    float Aa[DS], h[DS];
    bool fast = true;
    #pragma unroll
    for (int s = 0; s < DS; s++) {
        Aa[s] = -__expf(A_log[d * DS + s]);
        fast = fast && (fabsf(Aa[s] + (float)(s + 1)) < 1e-4f * (float)(s + 1));
        h[s] = 0.0f;
    }
    const float Dk = D_skip[d];

    const size_t rowbase = (size_t)b * TT * DI + d;
    const float* pdt = g_dt  + rowbase;
    const float* pxc = g_xc2 + rowbase;
    const float* pz  = g_z   + rowbase;
    float*       py  = g_y   + rowbase;
    const float4* pB = (const float4*)(g_Bm + (size_t)b * TT * DS);
    const float4* pC = (const float4*)(g_Cm + (size_t)b * TT * DS);

    if (fast) {
        for (int t = 0; t < TT; t++) {
            const size_t o = (size_t)t * DI;
            float dt = pdt[o], xc = pxc[o], z = pz[o];
            float Bv[DS], Cv[DS];
            #pragma unroll
            for (int q = 0; q < 4; q++) {
                float4 bq = pB[t*4 + q], cq = pC[t*4 + q];
                Bv[4*q]=bq.x; Bv[4*q+1]=bq.y; Bv[4*q+2]=bq.z; Bv[4*q+3]=bq.w;
                Cv[4*q]=cq.x; Cv[4*q+1]=cq.y; Cv[4*q+2]=cq.z; Cv[4*q+3]=cq.w;
            }
            const float du = dt * xc;
            const float w = __expf(-dt);
            float pw = w, y = 0.0f;
            #pragma unroll
            for (int s = 0; s < DS; s++) {
                h[s] = fmaf(pw, h[s], du * Bv[s]);
                y    = fmaf(h[s], Cv[s], y);
                pw  *= w;
            }
            y = fmaf(xc, Dk, y);
            py[o] = y * silu_f(z);
        }
    } else {
        for (int t = 0; t < TT; t++) {
            const size_t o = (size_t)t * DI;
            float dt = pdt[o], xc = pxc[o], z = pz[o];
            float Bv[DS], Cv[DS];
            #pragma unroll
            for (int q = 0; q < 4; q++) {
                float4 bq = pB[t*4 + q], cq = pC[t*4 + q];
                Bv[4*q]=bq.x; Bv[4*q+1]=bq.y; Bv[4*q+2]=bq.z; Bv[4*q+3]=bq.w;
                Cv[4*q]=cq.x; Cv[4*q+1]=cq.y; Cv[4*q+2]=cq.z; Cv[4*q+3]=cq.w;
            }
            const float du = dt * xc;
            float y = 0.0f;
            #pragma unroll
            for (int s = 0; s < DS; s++) {
                float dA = __expf(dt * Aa[s]);
                h[s] = fmaf(dA, h[s], du * Bv[s]);
                y    = fmaf(h[s], Cv[s], y);
            }
            y = fmaf(xc, Dk, y);
            py[o] = y * silu_f(z);
        }
    }
}

// ---------------- k5: out-proj GEMM (tf32, pair-major smem) + RMSNorm + residual ----
// Same 32-row x 256-col tiling / grid 400 as the measured-good build. ONLY change:
// smem stores tf32 element pairs (k, k+4) as uint2 in TRANSPOSED [pairIdx][row]
// layout -> each mma fragment fetch is one LDS.64 (halves LDS instruction count,
// conflict-free reads: byte offset 8*(4*lk+lr) is injective per 16-lane phase).
__global__ __launch_bounds__(256) void k5_gemm_out(const float* __restrict__ x,
                                                   const float* __restrict__ W,
                                                   const float* __restrict__ ln_w,
                                                   float* __restrict__ out) {
    __shared__ uint2 sA2[16 * 36];        // [pairIdx][row(32) pad->36]
    __shared__ uint2 sB2[16 * 260];       // [pairIdx][row(256) pad->260]
    __shared__ float rowsq[32];
    const int tid = threadIdx.x, lane = tid & 31, warp = tid >> 5;
    const int lr = lane >> 2, lk = lane & 3;
    const int m0 = blockIdx.x * 32;
    const int wr = (warp >> 2) * 16, wc = (warp & 3) * 64;

    if (tid < 32) rowsq[tid] = 0.0f;

    float acc[8][4];
    #pragma unroll
    for (int jj = 0; jj < 8; jj++)
        #pragma unroll
        for (int q = 0; q < 4; q++) acc[jj][q] = 0.0f;

    // A loader: 8 threads/row; thread q handles kk=q>>1, off=(q&1)*2
    const int ar = tid >> 3, aq = tid & 7;
    const int akk = aq >> 1, aoff = (aq & 1) * 2;
    const int br = tid;

    for (int d0 = 0; d0 < DI; d0 += 32) {
        __syncthreads();
        {
            const float* yrow = &g_y[(size_t)(m0 + ar) * DI + d0 + akk * 8 + aoff];
            float2 lo = *(const float2*)(yrow);       // k0+aoff, k0+aoff+1
            float2 hi = *(const float2*)(yrow + 4);   // k0+aoff+4, k0+aoff+5
            sA2[(akk * 4 + aoff    ) * 36 + ar] = make_uint2(f2t(lo.x), f2t(hi.x));
            sA2[(akk * 4 + aoff + 1) * 36 + ar] = make_uint2(f2t(lo.y), f2t(hi.y));
        }
        {
            const float4* p = (const float4*)(W + (size_t)br * DI + d0);
            #pragma unroll
            for (int kk = 0; kk < 4; kk++) {
                float4 v0 = p[2*kk], v1 = p[2*kk + 1];
                sB2[(kk * 4 + 0) * 260 + br] = make_uint2(f2t(v0.x), f2t(v1.x));
                sB2[(kk * 4 + 1) * 260 + br] = make_uint2(f2t(v0.y), f2t(v1.y));
                sB2[(kk * 4 + 2) * 260 + br] = make_uint2(f2t(v0.z), f2t(v1.z));
                sB2[(kk * 4 + 3) * 260 + br] = make_uint2(f2t(v0.w), f2t(v1.w));
            }
        }
        __syncthreads();
        #pragma unroll
        for (int kk = 0; kk < 4; kk++) {
            const int pidx = kk * 4 + lk;
            uint2 av0 = sA2[pidx * 36 + wr + lr];      // (a0, a2)
            uint2 av1 = sA2[pidx * 36 + wr + 8 + lr];  // (a1, a3)
            #pragma unroll
            for (int jj = 0; jj < 8; jj++) {
                uint2 bv = sB2[pidx * 260 + wc + 8*jj + lr];  // (b0, b1)
                mma8(acc[jj], av0.x, av1.x, av0.y, av1.y, bv.x, bv.y);
            }
        }
    }

    float s0 = 0.0f, s1 = 0.0f;
    #pragma unroll
    for (int jj = 0; jj < 8; jj++) {
        s0 += acc[jj][0]*acc[jj][0] + acc[jj][1]*acc[jj][1];
        s1 += acc[jj][2]*acc[jj][2] + acc[jj][3]*acc[jj][3];
    }
    s0 += __shfl_xor_sync(0xffffffffu, s0, 1); s0 += __shfl_xor_sync(0xffffffffu, s0, 2);
    s1 += __shfl_xor_sync(0xffffffffu, s1, 1); s1 += __shfl_xor_sync(0xffffffffu, s1, 2);
    if (lk == 0) { atomicAdd(&rowsq[wr + lr], s0); atomicAdd(&rowsq[wr + 8 + lr], s1); }
    __syncthreads();

    const int r0 = wr + lr, r1 = wr + 8 + lr;
    float rms0 = rsqrtf(rowsq[r0] * (1.0f / CC) + 1e-6f);
    float rms1 = rsqrtf(rowsq[r1] * (1.0f / CC) + 1e-6f);

    const int m0r = m0 + r0, m1r = m0 + r1;
    const int t0 = m0r & 63, b0_ = m0r >> 6, n_0 = b0_ / 25, j0 = b0_ - n_0 * 25;
    const int t1 = m1r & 63, b1_ = m1r >> 6, n_1 = b1_ / 25, j1 = b1_ - n_1 * 25;
    const size_t g0 = ((size_t)(n_0 * TT + t0) * JJ + j0) * CC;
    const size_t g1 = ((size_t)(n_1 * TT + t1) * JJ + j1) * CC;
    #pragma unroll
    for (int jj = 0; jj < 8; jj++) {
        const int col = wc + 8*jj + 2*lk;
        float2 lw = *(const float2*)&ln_w[col];
        float2 x0 = *(const float2*)&x[g0 + col];
        float2 x1 = *(const float2*)&x[g1 + col];
        *(float2*)&out[g0 + col] = make_float2(fmaf(acc[jj][0]*rms0, lw.x, x0.x),
                                               fmaf(acc[jj][1]*rms0, lw.y, x0.y));
        *(float2*)&out[g1 + col] = make_float2(fmaf(acc[jj][2]*rms1, lw.x, x1.x),
                                               fmaf(acc[jj][3]*rms1, lw.y, x1.y));
    }
}

// ---------------- launch ----------------
extern "C" void kernel_launch(void* const* d_in, const int* in_sizes, int n_in,
                              void* d_out, int out_size) {
    const float* x      = (const float*)d_in[0];
    const float* W_in   = (const float*)d_in[1];
    const float* conv_w = (const float*)d_in[2];
    const float* conv_b = (const float*)d_in[3];
    const float* W_xprj = (const float*)d_in[4];
    const float* W_dt   = (const float*)d_in[5];
    const float* b_dt   = (const float*)d_in[6];
    const float* A_log  = (const float*)d_in[7];
    const float* D_skip = (const float*)d_in[8];
    const float* W_out  = (const float*)d_in[9];
    const float* ln_w   = (const float*)d_in[10];
    float* out = (float*)d_out;

    k1_gemm_in<<<dim3(BTOT, 8), 256>>>(x, W_in);
    k2_conv<<<(NROWS * DI) / 256, 256>>>(conv_w, conv_b);
    k3_xproj<<<BTOT, 256>>>(W_xprj, W_dt, b_dt);
    k4_scan<<<dim3(BTOT, 4), 128>>>(A_log, D_skip);
    k5_gemm_out<<<NROWS / 32, 256>>>(x, W_out, ln_w, out);
}